// round 1
// baseline (speedup 1.0000x reference)
#include <cuda_runtime.h>
#include <cstddef>

#define DI 128
#define DO 64
#define TR 64
#define NMAX 100000

// Scratch: sx_ui, tx_iu (Nu*DO each), sx_iu, tx_ui (Ni*DO each),
// msg_ui (Ni*DO), msg_iu (Nu*DO), den_ui (Ni), den_iu (Nu), 4 score arrays.
__device__ __align__(16) float g_scratch[6 * (size_t)NMAX * DO + 6 * (size_t)NMAX];

// ---------------------------------------------------------------------------
// zero kernel (float4 main, scalar tail)
// ---------------------------------------------------------------------------
__global__ void zero_k(float* __restrict__ p, size_t nf) {
    size_t i = ((size_t)blockIdx.x * blockDim.x + threadIdx.x) * 4;
    if (i + 4 <= nf) {
        *(float4*)(p + i) = make_float4(0.f, 0.f, 0.f, 0.f);
    } else {
        for (; i < nf; i++) p[i] = 0.f;
    }
}

// ---------------------------------------------------------------------------
// Dual-output GEMM: Ya = X @ Wa, Yb = X @ Wb   (X:[N,128], W:[128,64])
// Tile: 64 rows x 128 cols (both W's), 256 threads, per-thread 4 rows x 8 cols.
// Thread t: tx = t&15, ty = t>>4. Cols = [4tx,4tx+4) of Ya and of Yb.
// This col mapping makes each LDS.128 phase read 8 contiguous bank-groups.
// ---------------------------------------------------------------------------
__global__ __launch_bounds__(256) void gemm_dual(
    const float* __restrict__ X, const float* __restrict__ Wa,
    const float* __restrict__ Wb, float* __restrict__ Ya,
    float* __restrict__ Yb, int N)
{
    extern __shared__ float sm[];
    float* Xs = sm;                    // TR x (DI+4)
    float* Ws = sm + TR * (DI + 4);    // DI x 128 (Wa cols 0..63, Wb cols 64..127)

    const int t = threadIdx.x;
    const int row0 = blockIdx.x * TR;

    // Load W tiles (8192 floats each, coalesced float4)
#pragma unroll
    for (int i = 0; i < 8; i++) {
        int idx = (i * 256 + t) * 4;
        int k = idx >> 6, c = idx & 63;
        *(float4*)&Ws[k * 128 + c]      = *(const float4*)&Wa[idx];
        *(float4*)&Ws[k * 128 + 64 + c] = *(const float4*)&Wb[idx];
    }
    // Load X tile (row-major in smem with +4 pad)
#pragma unroll
    for (int i = 0; i < 8; i++) {
        int idx = (i * 256 + t) * 4;
        int r = idx >> 7, k = idx & 127;
        float4 v = make_float4(0.f, 0.f, 0.f, 0.f);
        int row = row0 + r;
        if (row < N) v = *(const float4*)&X[(size_t)row * DI + k];
        *(float4*)&Xs[r * (DI + 4) + k] = v;
    }
    __syncthreads();

    const int tx = t & 15, ty = t >> 4;

    float acc[4][8];
#pragma unroll
    for (int i = 0; i < 4; i++)
#pragma unroll
        for (int j = 0; j < 8; j++) acc[i][j] = 0.f;

#pragma unroll 8
    for (int k = 0; k < DI; k++) {
        float4 w0 = *(const float4*)&Ws[k * 128 + tx * 4];        // Ya cols
        float4 w1 = *(const float4*)&Ws[k * 128 + 64 + tx * 4];   // Yb cols
        float xv0 = Xs[(ty * 4 + 0) * (DI + 4) + k];
        float xv1 = Xs[(ty * 4 + 1) * (DI + 4) + k];
        float xv2 = Xs[(ty * 4 + 2) * (DI + 4) + k];
        float xv3 = Xs[(ty * 4 + 3) * (DI + 4) + k];
        float xv[4] = {xv0, xv1, xv2, xv3};
#pragma unroll
        for (int i = 0; i < 4; i++) {
            acc[i][0] += xv[i] * w0.x;
            acc[i][1] += xv[i] * w0.y;
            acc[i][2] += xv[i] * w0.z;
            acc[i][3] += xv[i] * w0.w;
            acc[i][4] += xv[i] * w1.x;
            acc[i][5] += xv[i] * w1.y;
            acc[i][6] += xv[i] * w1.z;
            acc[i][7] += xv[i] * w1.w;
        }
    }

#pragma unroll
    for (int i = 0; i < 4; i++) {
        int row = row0 + ty * 4 + i;
        if (row < N) {
            *(float4*)&Ya[(size_t)row * DO + tx * 4] =
                make_float4(acc[i][0], acc[i][1], acc[i][2], acc[i][3]);
            *(float4*)&Yb[(size_t)row * DO + tx * 4] =
                make_float4(acc[i][4], acc[i][5], acc[i][6], acc[i][7]);
        }
    }
}

// ---------------------------------------------------------------------------
// Per-node score: s[n] = Y[n,:] . a[0:64]   (warp per node)
// ---------------------------------------------------------------------------
__global__ __launch_bounds__(256) void score_k(
    const float* __restrict__ Y, const float* __restrict__ a,
    float* __restrict__ s, int N)
{
    int w = blockIdx.x * 8 + (threadIdx.x >> 5);
    int lane = threadIdx.x & 31;
    if (w >= N) return;
    const float* y = Y + (size_t)w * DO;
    float v = y[lane] * a[lane] + y[lane + 32] * a[lane + 32];
#pragma unroll
    for (int o = 16; o; o >>= 1) v += __shfl_xor_sync(0xffffffffu, v, o);
    if (lane == 0) s[w] = v;
}

// ---------------------------------------------------------------------------
// Edge scatter: 16 lanes per edge, each lane handles one float4 of the 64-dim
// message. att = exp(leaky_relu(s_score[src] + t_score[tgt], 0.2)).
// ---------------------------------------------------------------------------
__global__ __launch_bounds__(256) void edge_k(
    const int* __restrict__ src, const int* __restrict__ tgt,
    const float* __restrict__ ss, const float* __restrict__ ts,
    const float4* __restrict__ sx4, float4* __restrict__ msg4,
    float* __restrict__ den, int E)
{
    int tid = blockIdx.x * blockDim.x + threadIdx.x;
    int e = tid >> 4;
    int lane = tid & 15;
    if (e >= E) return;

    int s = __ldg(&src[e]);
    int t = __ldg(&tgt[e]);
    float sc = __ldg(&ss[s]) + __ldg(&ts[t]);
    float sl = sc >= 0.f ? sc : 0.2f * sc;
    float att = expf(sl);

    float4 v = __ldg(&sx4[(size_t)s * 16 + lane]);
    float4* p = &msg4[(size_t)t * 16 + lane];
    asm volatile("red.global.add.v4.f32 [%0], {%1,%2,%3,%4};"
                 :: "l"(p), "f"(v.x * att), "f"(v.y * att),
                    "f"(v.z * att), "f"(v.w * att)
                 : "memory");
    if (lane == 0) atomicAdd(&den[t], att);
}

// ---------------------------------------------------------------------------
// Finalize: out = tx + msg / (den + eps)   (float4 per thread; 16 per node)
// ---------------------------------------------------------------------------
__global__ __launch_bounds__(256) void final_k(
    const float4* __restrict__ txp, const float4* __restrict__ msg,
    const float* __restrict__ den, float4* __restrict__ out, int n4)
{
    int i = blockIdx.x * blockDim.x + threadIdx.x;
    if (i >= n4) return;
    int node = i >> 4;
    float inv = 1.f / (den[node] + 1e-6f);
    float4 m = msg[i];
    float4 t = txp[i];
    out[i] = make_float4(t.x + m.x * inv, t.y + m.y * inv,
                         t.z + m.z * inv, t.w + m.w * inv);
}

// ---------------------------------------------------------------------------
extern "C" void kernel_launch(void* const* d_in, const int* in_sizes, int n_in,
                              void* d_out, int out_size)
{
    const float* x_user   = (const float*)d_in[0];
    const float* x_item   = (const float*)d_in[1];
    const float* W_ui_src = (const float*)d_in[2];
    const float* W_ui_tgt = (const float*)d_in[3];
    const float* W_iu_src = (const float*)d_in[4];
    const float* W_iu_tgt = (const float*)d_in[5];
    const float* a_ui     = (const float*)d_in[6];
    const float* a_iu     = (const float*)d_in[7];
    const int*   edge_ui  = (const int*)d_in[8];
    const int*   edge_iu  = (const int*)d_in[9];
    float* out = (float*)d_out;

    const int Nu  = in_sizes[0] / DI;
    const int Ni  = in_sizes[1] / DI;
    const int Eui = in_sizes[8] / 2;
    const int Eiu = in_sizes[9] / 2;

    float* base = nullptr;
    cudaGetSymbolAddress((void**)&base, g_scratch);

    float* s = base;
    float* sx_ui  = s; s += (size_t)Nu * DO;
    float* tx_iu  = s; s += (size_t)Nu * DO;
    float* sx_iu  = s; s += (size_t)Ni * DO;
    float* tx_ui  = s; s += (size_t)Ni * DO;
    float* msg_ui = s; s += (size_t)Ni * DO;
    float* msg_iu = s; s += (size_t)Nu * DO;
    float* den_ui = s; s += Ni;
    float* den_iu = s; s += Nu;
    float* ss_ui  = s; s += Nu;
    float* ts_ui  = s; s += Ni;
    float* ss_iu  = s; s += Ni;
    float* ts_iu  = s; s += Nu;

    const int SMEMB = (TR * (DI + 4) + DI * 128) * (int)sizeof(float); // 99328
    cudaFuncSetAttribute(gemm_dual, cudaFuncAttributeMaxDynamicSharedMemorySize, SMEMB);

    // Zero msg + den (contiguous region starting at msg_ui)
    {
        size_t zf = (size_t)(Ni + Nu) * DO + (size_t)Ni + (size_t)Nu;
        int blocks = (int)((zf / 4 + 255) / 256) + 1;
        zero_k<<<blocks, 256>>>(msg_ui, zf);
    }

    // Projections (fused dual-output per X)
    gemm_dual<<<(Nu + TR - 1) / TR, 256, SMEMB>>>(x_user, W_ui_src, W_iu_tgt, sx_ui, tx_iu, Nu);
    gemm_dual<<<(Ni + TR - 1) / TR, 256, SMEMB>>>(x_item, W_iu_src, W_ui_tgt, sx_iu, tx_ui, Ni);

    // Per-node attention score halves
    score_k<<<(Nu + 7) / 8, 256>>>(sx_ui, a_ui,      ss_ui, Nu);
    score_k<<<(Ni + 7) / 8, 256>>>(tx_ui, a_ui + DO, ts_ui, Ni);
    score_k<<<(Ni + 7) / 8, 256>>>(sx_iu, a_iu,      ss_iu, Ni);
    score_k<<<(Nu + 7) / 8, 256>>>(tx_iu, a_iu + DO, ts_iu, Nu);

    // Edge scatter (16 lanes per edge)
    {
        long long thr_ui = (long long)Eui * 16;
        long long thr_iu = (long long)Eiu * 16;
        edge_k<<<(int)((thr_ui + 255) / 256), 256>>>(
            edge_ui, edge_ui + Eui, ss_ui, ts_ui,
            (const float4*)sx_ui, (float4*)msg_ui, den_ui, Eui);
        edge_k<<<(int)((thr_iu + 255) / 256), 256>>>(
            edge_iu, edge_iu + Eiu, ss_iu, ts_iu,
            (const float4*)sx_iu, (float4*)msg_iu, den_iu, Eiu);
    }

    // Finalize: out_user then out_item
    {
        int n4u = Nu * 16, n4i = Ni * 16;
        final_k<<<(n4u + 255) / 256, 256>>>(
            (const float4*)tx_iu, (const float4*)msg_iu, den_iu,
            (float4*)out, n4u);
        final_k<<<(n4i + 255) / 256, 256>>>(
            (const float4*)tx_ui, (const float4*)msg_ui, den_ui,
            (float4*)(out + (size_t)Nu * DO), n4i);
    }
}

// round 2
// speedup vs baseline: 1.0879x; 1.0879x over previous
#include <cuda_runtime.h>
#include <cstddef>

#define DI 128
#define DO 64
#define TR 64
#define NMAX 100000

// Scratch: sx_ui, tx_iu (Nu*DO each), sx_iu, tx_ui (Ni*DO each),
// msg_ui (Ni*DO), msg_iu (Nu*DO), den_ui (Ni), den_iu (Nu), 4 score arrays.
__device__ __align__(16) float g_scratch[6 * (size_t)NMAX * DO + 6 * (size_t)NMAX];

// ---------------------------------------------------------------------------
// zero kernel (float4 main, scalar tail)
// ---------------------------------------------------------------------------
__global__ void zero_k(float* __restrict__ p, size_t nf) {
    size_t i = ((size_t)blockIdx.x * blockDim.x + threadIdx.x) * 4;
    if (i + 4 <= nf) {
        *(float4*)(p + i) = make_float4(0.f, 0.f, 0.f, 0.f);
    } else {
        for (; i < nf; i++) p[i] = 0.f;
    }
}

// ---------------------------------------------------------------------------
// Dual-output GEMM + fused per-node score epilogue:
//   Ya = X @ Wa, Yb = X @ Wb          (X:[N,128], W:[128,64])
//   sA[n] = Ya[n,:] . aA,  sB[n] = Yb[n,:] . aB
// Tile: 64 rows x 128 cols (both W's), 256 threads, per-thread 4 rows x 8 cols.
// Thread t: tx = t&15, ty = t>>4. Cols = [4tx,4tx+4) of Ya and of Yb.
// ---------------------------------------------------------------------------
__global__ __launch_bounds__(256) void gemm_dual(
    const float* __restrict__ X, const float* __restrict__ Wa,
    const float* __restrict__ Wb, float* __restrict__ Ya,
    float* __restrict__ Yb, const float* __restrict__ aA,
    const float* __restrict__ aB, float* __restrict__ sA,
    float* __restrict__ sB, int N)
{
    extern __shared__ float sm[];
    float* Xs = sm;                    // TR x (DI+4)
    float* Ws = sm + TR * (DI + 4);    // DI x 128 (Wa cols 0..63, Wb cols 64..127)

    const int t = threadIdx.x;
    const int row0 = blockIdx.x * TR;

    // Load W tiles (8192 floats each, coalesced float4)
#pragma unroll
    for (int i = 0; i < 8; i++) {
        int idx = (i * 256 + t) * 4;
        int k = idx >> 6, c = idx & 63;
        *(float4*)&Ws[k * 128 + c]      = *(const float4*)&Wa[idx];
        *(float4*)&Ws[k * 128 + 64 + c] = *(const float4*)&Wb[idx];
    }
    // Load X tile (row-major in smem with +4 pad)
#pragma unroll
    for (int i = 0; i < 8; i++) {
        int idx = (i * 256 + t) * 4;
        int r = idx >> 7, k = idx & 127;
        float4 v = make_float4(0.f, 0.f, 0.f, 0.f);
        int row = row0 + r;
        if (row < N) v = *(const float4*)&X[(size_t)row * DI + k];
        *(float4*)&Xs[r * (DI + 4) + k] = v;
    }

    const int tx = t & 15, ty = t >> 4;

    // Per-thread slices of the attention vectors (for the fused score)
    float aAr[4], aBr[4];
#pragma unroll
    for (int j = 0; j < 4; j++) {
        aAr[j] = __ldg(&aA[tx * 4 + j]);
        aBr[j] = __ldg(&aB[tx * 4 + j]);
    }

    __syncthreads();

    float acc[4][8];
#pragma unroll
    for (int i = 0; i < 4; i++)
#pragma unroll
        for (int j = 0; j < 8; j++) acc[i][j] = 0.f;

#pragma unroll 8
    for (int k = 0; k < DI; k++) {
        float4 w0 = *(const float4*)&Ws[k * 128 + tx * 4];        // Ya cols
        float4 w1 = *(const float4*)&Ws[k * 128 + 64 + tx * 4];   // Yb cols
        float xv0 = Xs[(ty * 4 + 0) * (DI + 4) + k];
        float xv1 = Xs[(ty * 4 + 1) * (DI + 4) + k];
        float xv2 = Xs[(ty * 4 + 2) * (DI + 4) + k];
        float xv3 = Xs[(ty * 4 + 3) * (DI + 4) + k];
        float xv[4] = {xv0, xv1, xv2, xv3};
#pragma unroll
        for (int i = 0; i < 4; i++) {
            acc[i][0] += xv[i] * w0.x;
            acc[i][1] += xv[i] * w0.y;
            acc[i][2] += xv[i] * w0.z;
            acc[i][3] += xv[i] * w0.w;
            acc[i][4] += xv[i] * w1.x;
            acc[i][5] += xv[i] * w1.y;
            acc[i][6] += xv[i] * w1.z;
            acc[i][7] += xv[i] * w1.w;
        }
    }

#pragma unroll
    for (int i = 0; i < 4; i++) {
        int row = row0 + ty * 4 + i;
        bool ok = row < N;
        if (ok) {
            *(float4*)&Ya[(size_t)row * DO + tx * 4] =
                make_float4(acc[i][0], acc[i][1], acc[i][2], acc[i][3]);
            *(float4*)&Yb[(size_t)row * DO + tx * 4] =
                make_float4(acc[i][4], acc[i][5], acc[i][6], acc[i][7]);
        }
        // Fused score: reduce over the 16 tx lanes (lane = (ty&1)*16 + tx,
        // so xor offsets 8/4/2/1 stay inside each 16-lane half-warp).
        float pA = acc[i][0] * aAr[0] + acc[i][1] * aAr[1] +
                   acc[i][2] * aAr[2] + acc[i][3] * aAr[3];
        float pB = acc[i][4] * aBr[0] + acc[i][5] * aBr[1] +
                   acc[i][6] * aBr[2] + acc[i][7] * aBr[3];
#pragma unroll
        for (int o = 8; o; o >>= 1) {
            pA += __shfl_xor_sync(0xffffffffu, pA, o);
            pB += __shfl_xor_sync(0xffffffffu, pB, o);
        }
        if (tx == 0 && ok) {
            sA[row] = pA;
            sB[row] = pB;
        }
    }
}

// ---------------------------------------------------------------------------
// Edge scatter: 16 lanes per edge, each lane handles one float4 of the 64-dim
// message. att = exp(leaky_relu(s_score[src] + t_score[tgt], 0.2)).
// ---------------------------------------------------------------------------
__global__ __launch_bounds__(256) void edge_k(
    const int* __restrict__ src, const int* __restrict__ tgt,
    const float* __restrict__ ss, const float* __restrict__ ts,
    const float4* __restrict__ sx4, float4* __restrict__ msg4,
    float* __restrict__ den, int E)
{
    int tid = blockIdx.x * blockDim.x + threadIdx.x;
    int e = tid >> 4;
    int lane = tid & 15;
    if (e >= E) return;

    int s = __ldg(&src[e]);
    int t = __ldg(&tgt[e]);
    float sc = __ldg(&ss[s]) + __ldg(&ts[t]);
    float sl = sc >= 0.f ? sc : 0.2f * sc;
    float att = expf(sl);

    float4 v = __ldg(&sx4[(size_t)s * 16 + lane]);
    float4* p = &msg4[(size_t)t * 16 + lane];
    asm volatile("red.global.add.v4.f32 [%0], {%1,%2,%3,%4};"
                 :: "l"(p), "f"(v.x * att), "f"(v.y * att),
                    "f"(v.z * att), "f"(v.w * att)
                 : "memory");
    if (lane == 0) atomicAdd(&den[t], att);
}

// ---------------------------------------------------------------------------
// Finalize: out = tx + msg / (den + eps)   (float4 per thread; 16 per node)
// ---------------------------------------------------------------------------
__global__ __launch_bounds__(256) void final_k(
    const float4* __restrict__ txp, const float4* __restrict__ msg,
    const float* __restrict__ den, float4* __restrict__ out, int n4)
{
    int i = blockIdx.x * blockDim.x + threadIdx.x;
    if (i >= n4) return;
    int node = i >> 4;
    float inv = 1.f / (den[node] + 1e-6f);
    float4 m = msg[i];
    float4 t = txp[i];
    out[i] = make_float4(t.x + m.x * inv, t.y + m.y * inv,
                         t.z + m.z * inv, t.w + m.w * inv);
}

// ---------------------------------------------------------------------------
extern "C" void kernel_launch(void* const* d_in, const int* in_sizes, int n_in,
                              void* d_out, int out_size)
{
    const float* x_user   = (const float*)d_in[0];
    const float* x_item   = (const float*)d_in[1];
    const float* W_ui_src = (const float*)d_in[2];
    const float* W_ui_tgt = (const float*)d_in[3];
    const float* W_iu_src = (const float*)d_in[4];
    const float* W_iu_tgt = (const float*)d_in[5];
    const float* a_ui     = (const float*)d_in[6];
    const float* a_iu     = (const float*)d_in[7];
    const int*   edge_ui  = (const int*)d_in[8];
    const int*   edge_iu  = (const int*)d_in[9];
    float* out = (float*)d_out;

    const int Nu  = in_sizes[0] / DI;
    const int Ni  = in_sizes[1] / DI;
    const int Eui = in_sizes[8] / 2;
    const int Eiu = in_sizes[9] / 2;

    float* base = nullptr;
    cudaGetSymbolAddress((void**)&base, g_scratch);

    float* s = base;
    float* sx_ui  = s; s += (size_t)Nu * DO;
    float* tx_iu  = s; s += (size_t)Nu * DO;
    float* sx_iu  = s; s += (size_t)Ni * DO;
    float* tx_ui  = s; s += (size_t)Ni * DO;
    float* msg_ui = s; s += (size_t)Ni * DO;
    float* msg_iu = s; s += (size_t)Nu * DO;
    float* den_ui = s; s += Ni;
    float* den_iu = s; s += Nu;
    float* ss_ui  = s; s += Nu;
    float* ts_ui  = s; s += Ni;
    float* ss_iu  = s; s += Ni;
    float* ts_iu  = s; s += Nu;

    const int SMEMB = (TR * (DI + 4) + DI * 128) * (int)sizeof(float); // 99328
    cudaFuncSetAttribute(gemm_dual, cudaFuncAttributeMaxDynamicSharedMemorySize, SMEMB);

    // Zero msg + den (contiguous region starting at msg_ui)
    {
        size_t zf = (size_t)(Ni + Nu) * DO + (size_t)Ni + (size_t)Nu;
        int blocks = (int)((zf / 4 + 255) / 256) + 1;
        zero_k<<<blocks, 256>>>(msg_ui, zf);
    }

    // Projections (fused dual-output per X) + fused node scores.
    // Launch1: Ya=sx_ui (score a_ui[0:64] -> ss_ui), Yb=tx_iu (a_iu[64:128] -> ts_iu)
    gemm_dual<<<(Nu + TR - 1) / TR, 256, SMEMB>>>(
        x_user, W_ui_src, W_iu_tgt, sx_ui, tx_iu,
        a_ui, a_iu + DO, ss_ui, ts_iu, Nu);
    // Launch2: Ya=sx_iu (a_iu[0:64] -> ss_iu), Yb=tx_ui (a_ui[64:128] -> ts_ui)
    gemm_dual<<<(Ni + TR - 1) / TR, 256, SMEMB>>>(
        x_item, W_iu_src, W_ui_tgt, sx_iu, tx_ui,
        a_iu, a_ui + DO, ss_iu, ts_ui, Ni);

    // Edge scatter (16 lanes per edge)
    {
        long long thr_ui = (long long)Eui * 16;
        long long thr_iu = (long long)Eiu * 16;
        edge_k<<<(int)((thr_ui + 255) / 256), 256>>>(
            edge_ui, edge_ui + Eui, ss_ui, ts_ui,
            (const float4*)sx_ui, (float4*)msg_ui, den_ui, Eui);
        edge_k<<<(int)((thr_iu + 255) / 256), 256>>>(
            edge_iu, edge_iu + Eiu, ss_iu, ts_iu,
            (const float4*)sx_iu, (float4*)msg_iu, den_iu, Eiu);
    }

    // Finalize: out_user then out_item
    {
        int n4u = Nu * 16, n4i = Ni * 16;
        final_k<<<(n4u + 255) / 256, 256>>>(
            (const float4*)tx_iu, (const float4*)msg_iu, den_iu,
            (float4*)out, n4u);
        final_k<<<(n4i + 255) / 256, 256>>>(
            (const float4*)tx_ui, (const float4*)msg_ui, den_ui,
            (float4*)(out + (size_t)Nu * DO), n4i);
    }
}

// round 4
// speedup vs baseline: 1.3908x; 1.2784x over previous
#include <cuda_runtime.h>
#include <cuda_bf16.h>
#include <cstdint>
#include <cstddef>

#define DI 128
#define DO 64
#define NMAX 100000

// B image layout: [128 n][136 k-pitch] bf16 (272B row pitch)
#define BPITCH 136

// ---------------------------------------------------------------------------
// Scratch
// ---------------------------------------------------------------------------
__device__ __align__(16) float g_scratch[6 * (size_t)NMAX * DO + 6 * (size_t)NMAX];
__device__ __align__(16) __nv_bfloat16 g_B1hi[128 * BPITCH], g_B1lo[128 * BPITCH];
__device__ __align__(16) __nv_bfloat16 g_B2hi[128 * BPITCH], g_B2lo[128 * BPITCH];

__device__ __forceinline__ uint32_t smem_u32(const void* p) {
    uint32_t a;
    asm("{ .reg .u64 t; cvta.to.shared.u64 t, %1; cvt.u32.u64 %0, t; }"
        : "=r"(a) : "l"(p));
    return a;
}

__device__ __forceinline__ void ldm_x4(uint32_t* r, uint32_t addr) {
    asm volatile("ldmatrix.sync.aligned.m8n8.x4.shared.b16 {%0,%1,%2,%3}, [%4];"
                 : "=r"(r[0]), "=r"(r[1]), "=r"(r[2]), "=r"(r[3]) : "r"(addr));
}

__device__ __forceinline__ void mma_bf16(float* c, const uint32_t* a,
                                         uint32_t b0, uint32_t b1) {
    asm volatile("mma.sync.aligned.m16n8k16.row.col.f32.bf16.bf16.f32 "
                 "{%0,%1,%2,%3}, {%4,%5,%6,%7}, {%8,%9}, {%0,%1,%2,%3};"
                 : "+f"(c[0]), "+f"(c[1]), "+f"(c[2]), "+f"(c[3])
                 : "r"(a[0]), "r"(a[1]), "r"(a[2]), "r"(a[3]),
                   "r"(b0), "r"(b1));
}

// SMEM layout (bytes). X/B tiles: 128 rows x 272B pitch (128 bf16 + 8 pad)
#define XPITCH 272
#define OFF_A    0                       // aA[64], aB[64] floats (512B)
#define OFF_XHI  512
#define OFF_XLO  (OFF_XHI + 128 * XPITCH)
#define OFF_BHI  (OFF_XLO + 128 * XPITCH)
#define OFF_BLO  (OFF_BHI + 128 * XPITCH)
#define SMEM_TOT (OFF_BLO + 128 * XPITCH)   // 139776

// ---------------------------------------------------------------------------
// Prep: B[n][k] = Wa[k][n] (n<64) else Wb[k][n-64], split into bf16 hi/lo,
// stored [n][BPITCH] so plain (non-trans) ldmatrix yields the mma B fragment.
// ---------------------------------------------------------------------------
__global__ void pre_w_k(const float* __restrict__ Wa, const float* __restrict__ Wb,
                        __nv_bfloat16* __restrict__ Bhi, __nv_bfloat16* __restrict__ Blo) {
    int idx = blockIdx.x * 256 + threadIdx.x;
    if (idx >= 128 * 128) return;
    int n = idx >> 7, k = idx & 127;
    float w = (n < 64) ? Wa[k * 64 + n] : Wb[k * 64 + (n - 64)];
    __nv_bfloat16 hi = __float2bfloat16(w);
    __nv_bfloat16 lo = __float2bfloat16(w - __bfloat162float(hi));
    Bhi[n * BPITCH + k] = hi;
    Blo[n * BPITCH + k] = lo;
}

// ---------------------------------------------------------------------------
// zero kernel
// ---------------------------------------------------------------------------
__global__ void zero_k(float* __restrict__ p, size_t nf) {
    size_t i = ((size_t)blockIdx.x * blockDim.x + threadIdx.x) * 4;
    if (i + 4 <= nf) {
        *(float4*)(p + i) = make_float4(0.f, 0.f, 0.f, 0.f);
    } else {
        for (; i < nf; i++) p[i] = 0.f;
    }
}

// ---------------------------------------------------------------------------
// HMMA GEMM: M-tile 128, N=128 (Ya cols 0..63, Yb 64..127), K=128.
// Split-bf16: D = Xhi*Bhi + Xhi*Blo + Xlo*Bhi (fp32 acc).
// 8 warps; warp w owns rows w*16..w*16+15. Fused per-row score epilogue.
// ---------------------------------------------------------------------------
__global__ __launch_bounds__(256)
void gemm_tc(const float* __restrict__ X,
             const __nv_bfloat16* __restrict__ Bhi, const __nv_bfloat16* __restrict__ Blo,
             float* __restrict__ Ya, float* __restrict__ Yb,
             const float* __restrict__ aA, const float* __restrict__ aB,
             float* __restrict__ sA, float* __restrict__ sB, int N)
{
    extern __shared__ char sm[];
    const uint32_t sb = smem_u32(sm);
    const int tid = threadIdx.x, wid = tid >> 5, lane = tid & 31;
    const int row0 = blockIdx.x * 128;

    // Copy pre-split B images into smem (layout identical: [128][BPITCH])
    {
        const float4* bh = (const float4*)Bhi;
        const float4* bl = (const float4*)Blo;
        float4* sh = (float4*)(sm + OFF_BHI);
        float4* sl = (float4*)(sm + OFF_BLO);
        const int n4 = 128 * BPITCH * 2 / 16;   // 2176 float4
        for (int i = tid; i < n4; i += 256) {
            sh[i] = bh[i];
            sl[i] = bl[i];
        }
    }
    if (tid < 64)       ((float*)(sm + OFF_A))[tid] = __ldg(&aA[tid]);
    else if (tid < 128) ((float*)(sm + OFF_A))[tid] = __ldg(&aB[tid - 64]);

    // Load + split X tile [128 rows x 128 k] into hi/lo smem images
#pragma unroll
    for (int i = 0; i < 16; i++) {
        int idx = i * 256 + tid;            // 4096 float4 loads
        int r = idx >> 5;
        int k0 = (idx & 31) * 4;
        float4 v = make_float4(0.f, 0.f, 0.f, 0.f);
        if (row0 + r < N) v = *(const float4*)&X[(size_t)(row0 + r) * DI + k0];
        __nv_bfloat16 h0 = __float2bfloat16(v.x), h1 = __float2bfloat16(v.y);
        __nv_bfloat16 h2 = __float2bfloat16(v.z), h3 = __float2bfloat16(v.w);
        __nv_bfloat16 l0 = __float2bfloat16(v.x - __bfloat162float(h0));
        __nv_bfloat16 l1 = __float2bfloat16(v.y - __bfloat162float(h1));
        __nv_bfloat16 l2 = __float2bfloat16(v.z - __bfloat162float(h2));
        __nv_bfloat16 l3 = __float2bfloat16(v.w - __bfloat162float(h3));
        __nv_bfloat162 hp0, hp1, lp0, lp1;
        hp0.x = h0; hp0.y = h1; hp1.x = h2; hp1.y = h3;
        lp0.x = l0; lp0.y = l1; lp1.x = l2; lp1.y = l3;
        uint32_t off = r * XPITCH + k0 * 2;
        *(uint2*)(sm + OFF_XHI + off) = make_uint2(*(uint32_t*)&hp0, *(uint32_t*)&hp1);
        *(uint2*)(sm + OFF_XLO + off) = make_uint2(*(uint32_t*)&lp0, *(uint32_t*)&lp1);
    }
    __syncthreads();

    // Accumulators: 16 n-tiles (0..7 -> Ya, 8..15 -> Yb), 4 f32 each
    float c[16][4];
#pragma unroll
    for (int j = 0; j < 16; j++)
#pragma unroll
        for (int q = 0; q < 4; q++) c[j][q] = 0.f;

    // ldmatrix lane-address components
    const int arow = wid * 16 + (lane & 7) + ((lane >> 3) & 1) * 8;
    const int akk  = (lane >> 4) * 8;
    const int brow = (lane & 7) + ((lane >> 4) & 1) * 8;
    const int bkk  = ((lane >> 3) & 1) * 8;

#pragma unroll
    for (int s = 0; s < 8; s++) {
        const int ks = s * 16;
        uint32_t ah[4], al[4];
        ldm_x4(ah, sb + OFF_XHI + arow * XPITCH + (ks + akk) * 2);
        ldm_x4(al, sb + OFF_XLO + arow * XPITCH + (ks + akk) * 2);
#pragma unroll
        for (int p = 0; p < 8; p++) {
            uint32_t bh[4], bl[4];
            uint32_t boff = (p * 16 + brow) * XPITCH + (ks + bkk) * 2;
            ldm_x4(bh, sb + OFF_BHI + boff);
            ldm_x4(bl, sb + OFF_BLO + boff);
            mma_bf16(c[2 * p],     ah, bh[0], bh[1]);
            mma_bf16(c[2 * p],     ah, bl[0], bl[1]);
            mma_bf16(c[2 * p],     al, bh[0], bh[1]);
            mma_bf16(c[2 * p + 1], ah, bh[2], bh[3]);
            mma_bf16(c[2 * p + 1], ah, bl[2], bl[3]);
            mma_bf16(c[2 * p + 1], al, bh[2], bh[3]);
        }
    }

    // Epilogue: C fragment rows r0 = lane/4, r1 = r0+8 (warp-local)
    const int r0g = row0 + wid * 16 + (lane >> 2);
    const int r1g = r0g + 8;
    const bool ok0 = r0g < N, ok1 = r1g < N;
    const float* aS = (const float*)(sm + OFF_A);
    const int cp = (lane & 3) * 2;

    float s0A = 0.f, s1A = 0.f, s0B = 0.f, s1B = 0.f;
#pragma unroll
    for (int j = 0; j < 8; j++) {
        int col = j * 8 + cp;
        float a0 = aS[col], a1 = aS[col + 1];
        s0A += c[j][0] * a0 + c[j][1] * a1;
        s1A += c[j][2] * a0 + c[j][3] * a1;
        float b0 = aS[64 + col], b1 = aS[64 + col + 1];
        s0B += c[j + 8][0] * b0 + c[j + 8][1] * b1;
        s1B += c[j + 8][2] * b0 + c[j + 8][3] * b1;
        if (ok0) {
            *(float2*)&Ya[(size_t)r0g * DO + col] = make_float2(c[j][0], c[j][1]);
            *(float2*)&Yb[(size_t)r0g * DO + col] = make_float2(c[j + 8][0], c[j + 8][1]);
        }
        if (ok1) {
            *(float2*)&Ya[(size_t)r1g * DO + col] = make_float2(c[j][2], c[j][3]);
            *(float2*)&Yb[(size_t)r1g * DO + col] = make_float2(c[j + 8][2], c[j + 8][3]);
        }
    }
    // Reduce over the 4 lanes sharing a row (lane&3)
#pragma unroll
    for (int o = 1; o <= 2; o <<= 1) {
        s0A += __shfl_xor_sync(0xffffffffu, s0A, o);
        s1A += __shfl_xor_sync(0xffffffffu, s1A, o);
        s0B += __shfl_xor_sync(0xffffffffu, s0B, o);
        s1B += __shfl_xor_sync(0xffffffffu, s1B, o);
    }
    if ((lane & 3) == 0) {
        if (ok0) { sA[r0g] = s0A; sB[r0g] = s0B; }
        if (ok1) { sA[r1g] = s1A; sB[r1g] = s1B; }
    }
}

// ---------------------------------------------------------------------------
// Edge scatter: 16 lanes per edge, 4 edges per group (batched gathers, MLP=4)
// ---------------------------------------------------------------------------
__global__ __launch_bounds__(256) void edge_k(
    const int* __restrict__ src, const int* __restrict__ tgt,
    const float* __restrict__ ss, const float* __restrict__ ts,
    const float4* __restrict__ sx4, float4* __restrict__ msg4,
    float* __restrict__ den, int E)
{
    int g = blockIdx.x * 16 + (threadIdx.x >> 4);
    int lane = threadIdx.x & 15;
    int e0 = g * 4;
    if (e0 >= E) return;
    int n = E - e0; if (n > 4) n = 4;

    int s[4], t[4];
#pragma unroll
    for (int j = 0; j < 4; j++) {
        int e = e0 + (j < n ? j : 0);
        s[j] = __ldg(&src[e]);
        t[j] = __ldg(&tgt[e]);
    }
    float att[4];
#pragma unroll
    for (int j = 0; j < 4; j++) {
        float sc = __ldg(&ss[s[j]]) + __ldg(&ts[t[j]]);
        float sl = sc >= 0.f ? sc : 0.2f * sc;
        att[j] = expf(sl);
    }
    float4 v[4];
#pragma unroll
    for (int j = 0; j < 4; j++) v[j] = __ldg(&sx4[(size_t)s[j] * 16 + lane]);
#pragma unroll
    for (int j = 0; j < 4; j++) {
        if (j < n) {
            float4* p = &msg4[(size_t)t[j] * 16 + lane];
            asm volatile("red.global.add.v4.f32 [%0], {%1,%2,%3,%4};"
                         :: "l"(p), "f"(v[j].x * att[j]), "f"(v[j].y * att[j]),
                            "f"(v[j].z * att[j]), "f"(v[j].w * att[j]) : "memory");
            if (lane == 0) atomicAdd(&den[t[j]], att[j]);
        }
    }
}

// ---------------------------------------------------------------------------
// Finalize: out = tx + msg / (den + eps)
// ---------------------------------------------------------------------------
__global__ __launch_bounds__(256) void final_k(
    const float4* __restrict__ txp, const float4* __restrict__ msg,
    const float* __restrict__ den, float4* __restrict__ out, int n4)
{
    int i = blockIdx.x * blockDim.x + threadIdx.x;
    if (i >= n4) return;
    int node = i >> 4;
    float inv = 1.f / (den[node] + 1e-6f);
    float4 m = msg[i];
    float4 t = txp[i];
    out[i] = make_float4(t.x + m.x * inv, t.y + m.y * inv,
                         t.z + m.z * inv, t.w + m.w * inv);
}

// ---------------------------------------------------------------------------
extern "C" void kernel_launch(void* const* d_in, const int* in_sizes, int n_in,
                              void* d_out, int out_size)
{
    const float* x_user   = (const float*)d_in[0];
    const float* x_item   = (const float*)d_in[1];
    const float* W_ui_src = (const float*)d_in[2];
    const float* W_ui_tgt = (const float*)d_in[3];
    const float* W_iu_src = (const float*)d_in[4];
    const float* W_iu_tgt = (const float*)d_in[5];
    const float* a_ui     = (const float*)d_in[6];
    const float* a_iu     = (const float*)d_in[7];
    const int*   edge_ui  = (const int*)d_in[8];
    const int*   edge_iu  = (const int*)d_in[9];
    float* out = (float*)d_out;

    const int Nu  = in_sizes[0] / DI;
    const int Ni  = in_sizes[1] / DI;
    const int Eui = in_sizes[8] / 2;
    const int Eiu = in_sizes[9] / 2;

    float* base = nullptr;
    cudaGetSymbolAddress((void**)&base, g_scratch);
    __nv_bfloat16 *B1hi, *B1lo, *B2hi, *B2lo;
    cudaGetSymbolAddress((void**)&B1hi, g_B1hi);
    cudaGetSymbolAddress((void**)&B1lo, g_B1lo);
    cudaGetSymbolAddress((void**)&B2hi, g_B2hi);
    cudaGetSymbolAddress((void**)&B2lo, g_B2lo);

    float* s = base;
    float* sx_ui  = s; s += (size_t)Nu * DO;
    float* tx_iu  = s; s += (size_t)Nu * DO;
    float* sx_iu  = s; s += (size_t)Ni * DO;
    float* tx_ui  = s; s += (size_t)Ni * DO;
    float* msg_ui = s; s += (size_t)Ni * DO;
    float* msg_iu = s; s += (size_t)Nu * DO;
    float* den_ui = s; s += Ni;
    float* den_iu = s; s += Nu;
    float* ss_ui  = s; s += Nu;
    float* ts_ui  = s; s += Ni;
    float* ss_iu  = s; s += Ni;
    float* ts_iu  = s; s += Nu;

    cudaFuncSetAttribute(gemm_tc, cudaFuncAttributeMaxDynamicSharedMemorySize, SMEM_TOT);

    // Zero msg + den
    {
        size_t zf = (size_t)(Ni + Nu) * DO + (size_t)Ni + (size_t)Nu;
        int blocks = (int)((zf / 4 + 255) / 256) + 1;
        zero_k<<<blocks, 256>>>(msg_ui, zf);
    }

    // Prep split/transposed B images
    pre_w_k<<<64, 256>>>(W_ui_src, W_iu_tgt, B1hi, B1lo);
    pre_w_k<<<64, 256>>>(W_iu_src, W_ui_tgt, B2hi, B2lo);

    // HMMA projections + fused node scores
    gemm_tc<<<(Nu + 127) / 128, 256, SMEM_TOT>>>(
        x_user, B1hi, B1lo, sx_ui, tx_iu, a_ui, a_iu + DO, ss_ui, ts_iu, Nu);
    gemm_tc<<<(Ni + 127) / 128, 256, SMEM_TOT>>>(
        x_item, B2hi, B2lo, sx_iu, tx_ui, a_iu, a_ui + DO, ss_iu, ts_ui, Ni);

    // Edge scatter (4 edges per 16-lane group)
    edge_k<<<(Eui + 63) / 64, 256>>>(
        edge_ui, edge_ui + Eui, ss_ui, ts_ui,
        (const float4*)sx_ui, (float4*)msg_ui, den_ui, Eui);
    edge_k<<<(Eiu + 63) / 64, 256>>>(
        edge_iu, edge_iu + Eiu, ss_iu, ts_iu,
        (const float4*)sx_iu, (float4*)msg_iu, den_iu, Eiu);

    // Finalize
    {
        int n4u = Nu * 16, n4i = Ni * 16;
        final_k<<<(n4u + 255) / 256, 256>>>(
            (const float4*)tx_iu, (const float4*)msg_iu, den_iu,
            (float4*)out, n4u);
        final_k<<<(n4i + 255) / 256, 256>>>(
            (const float4*)tx_ui, (const float4*)msg_ui, den_ui,
            (float4*)(out + (size_t)Nu * DO), n4i);
    }
}

// round 5
// speedup vs baseline: 1.5394x; 1.1068x over previous
#include <cuda_runtime.h>
#include <cuda_bf16.h>
#include <cstdint>
#include <cstddef>

#define DI 128
#define DO 64
#define NMAX 100000

// B image layout: [128 n][136 k-pitch] bf16 (272B row pitch)
#define BPITCH 136

// ---------------------------------------------------------------------------
// Scratch
// ---------------------------------------------------------------------------
__device__ __align__(16) float g_scratch[6 * (size_t)NMAX * DO + 6 * (size_t)NMAX];
__device__ __align__(16) __nv_bfloat16 g_B1hi[128 * BPITCH], g_B1lo[128 * BPITCH];
__device__ __align__(16) __nv_bfloat16 g_B2hi[128 * BPITCH], g_B2lo[128 * BPITCH];

__device__ __forceinline__ uint32_t smem_u32(const void* p) {
    uint32_t a;
    asm("{ .reg .u64 t; cvta.to.shared.u64 t, %1; cvt.u32.u64 %0, t; }"
        : "=r"(a) : "l"(p));
    return a;
}

__device__ __forceinline__ void ldm_x4(uint32_t* r, uint32_t addr) {
    asm volatile("ldmatrix.sync.aligned.m8n8.x4.shared.b16 {%0,%1,%2,%3}, [%4];"
                 : "=r"(r[0]), "=r"(r[1]), "=r"(r[2]), "=r"(r[3]) : "r"(addr));
}

__device__ __forceinline__ void mma_bf16(float* c, const uint32_t* a,
                                         uint32_t b0, uint32_t b1) {
    asm volatile("mma.sync.aligned.m16n8k16.row.col.f32.bf16.bf16.f32 "
                 "{%0,%1,%2,%3}, {%4,%5,%6,%7}, {%8,%9}, {%0,%1,%2,%3};"
                 : "+f"(c[0]), "+f"(c[1]), "+f"(c[2]), "+f"(c[3])
                 : "r"(a[0]), "r"(a[1]), "r"(a[2]), "r"(a[3]),
                   "r"(b0), "r"(b1));
}

// Pack two floats into bf16x2 (hi) and the residual bf16x2 (lo)
__device__ __forceinline__ void split2(float x, float y, uint32_t& hi, uint32_t& lo) {
    __nv_bfloat162 h = __floats2bfloat162_rn(x, y);
    __nv_bfloat162 l = __floats2bfloat162_rn(x - __bfloat162float(h.x),
                                             y - __bfloat162float(h.y));
    hi = *(uint32_t*)&h;
    lo = *(uint32_t*)&l;
}

// SMEM layout (bytes). B tiles: 128 rows x 272B pitch
#define XPITCH 272
#define OFF_A    0                       // aA[64], aB[64] floats (512B)
#define OFF_BHI  512
#define OFF_BLO  (OFF_BHI + 128 * XPITCH)
#define SMEM_TOT (OFF_BLO + 128 * XPITCH)   // 70144

// ---------------------------------------------------------------------------
// Prep: B[n][k] = Wa[k][n] (n<64) else Wb[k][n-64], split into bf16 hi/lo,
// stored [n][BPITCH] so plain (non-trans) ldmatrix yields the mma B fragment.
// ---------------------------------------------------------------------------
__global__ void pre_w_k(const float* __restrict__ Wa, const float* __restrict__ Wb,
                        __nv_bfloat16* __restrict__ Bhi, __nv_bfloat16* __restrict__ Blo) {
    int idx = blockIdx.x * 256 + threadIdx.x;
    if (idx >= 128 * 128) return;
    int n = idx >> 7, k = idx & 127;
    float w = (n < 64) ? Wa[k * 64 + n] : Wb[k * 64 + (n - 64)];
    __nv_bfloat16 hi = __float2bfloat16(w);
    __nv_bfloat16 lo = __float2bfloat16(w - __bfloat162float(hi));
    Bhi[n * BPITCH + k] = hi;
    Blo[n * BPITCH + k] = lo;
}

// ---------------------------------------------------------------------------
// zero kernel
// ---------------------------------------------------------------------------
__global__ void zero_k(float* __restrict__ p, size_t nf) {
    size_t i = ((size_t)blockIdx.x * blockDim.x + threadIdx.x) * 4;
    if (i + 4 <= nf) {
        *(float4*)(p + i) = make_float4(0.f, 0.f, 0.f, 0.f);
    } else {
        for (; i < nf; i++) p[i] = 0.f;
    }
}

// ---------------------------------------------------------------------------
// HMMA GEMM: M-tile 128, N=128 (Ya cols 0..63, Yb 64..127), K=128.
// Split-bf16: D = Xhi*Bhi + Xhi*Blo + Xlo*Bhi (fp32 acc).
// X fragments loaded DIRECTLY from gmem (no smem staging) and split in regs.
// 8 warps; warp w owns rows w*16..w*16+15. 2 CTAs/SM. Fused score epilogue.
// ---------------------------------------------------------------------------
__global__ __launch_bounds__(256, 2)
void gemm_tc(const float* __restrict__ X,
             const __nv_bfloat16* __restrict__ Bhi, const __nv_bfloat16* __restrict__ Blo,
             float* __restrict__ Ya, float* __restrict__ Yb,
             const float* __restrict__ aA, const float* __restrict__ aB,
             float* __restrict__ sA, float* __restrict__ sB, int N)
{
    extern __shared__ char sm[];
    const uint32_t sb = smem_u32(sm);
    const int tid = threadIdx.x, wid = tid >> 5, lane = tid & 31;
    const int row0 = blockIdx.x * 128;

    // Copy pre-split B images into smem (layout identical: [128][BPITCH])
    {
        const float4* bh = (const float4*)Bhi;
        const float4* bl = (const float4*)Blo;
        float4* sh = (float4*)(sm + OFF_BHI);
        float4* sl = (float4*)(sm + OFF_BLO);
        const int n4 = 128 * BPITCH * 2 / 16;   // 2176 float4
        for (int i = tid; i < n4; i += 256) {
            sh[i] = bh[i];
            sl[i] = bl[i];
        }
    }
    if (tid < 64)       ((float*)(sm + OFF_A))[tid] = __ldg(&aA[tid]);
    else if (tid < 128) ((float*)(sm + OFF_A))[tid] = __ldg(&aB[tid - 64]);

    // A-fragment source rows/cols (mma m16n8k16 layout)
    const int r0g = row0 + wid * 16 + (lane >> 2);
    const int r1g = r0g + 8;
    const bool ok0 = r0g < N, ok1 = r1g < N;
    const int c0 = (lane & 3) * 2;
    const float* x0 = X + (size_t)(ok0 ? r0g : 0) * DI + c0;
    const float* x1 = X + (size_t)(ok1 ? r1g : 0) * DI + c0;

    __syncthreads();

    // Accumulators: 16 n-tiles (0..7 -> Ya, 8..15 -> Yb), 4 f32 each
    float c[16][4];
#pragma unroll
    for (int j = 0; j < 16; j++)
#pragma unroll
        for (int q = 0; q < 4; q++) c[j][q] = 0.f;

    // ldmatrix B lane-address components
    const int brow = (lane & 7) + ((lane >> 4) & 1) * 8;
    const int bkk  = ((lane >> 3) & 1) * 8;

#pragma unroll
    for (int s = 0; s < 8; s++) {
        const int ks = s * 16;
        // Load A fragment straight from gmem
        float2 v00 = ok0 ? *(const float2*)(x0 + ks)     : make_float2(0.f, 0.f);
        float2 v10 = ok1 ? *(const float2*)(x1 + ks)     : make_float2(0.f, 0.f);
        float2 v01 = ok0 ? *(const float2*)(x0 + ks + 8) : make_float2(0.f, 0.f);
        float2 v11 = ok1 ? *(const float2*)(x1 + ks + 8) : make_float2(0.f, 0.f);
        uint32_t ah[4], al[4];
        split2(v00.x, v00.y, ah[0], al[0]);
        split2(v10.x, v10.y, ah[1], al[1]);
        split2(v01.x, v01.y, ah[2], al[2]);
        split2(v11.x, v11.y, ah[3], al[3]);

#pragma unroll
        for (int p = 0; p < 8; p++) {
            uint32_t bh[4], bl[4];
            uint32_t boff = (p * 16 + brow) * XPITCH + (ks + bkk) * 2;
            ldm_x4(bh, sb + OFF_BHI + boff);
            ldm_x4(bl, sb + OFF_BLO + boff);
            mma_bf16(c[2 * p],     ah, bh[0], bh[1]);
            mma_bf16(c[2 * p],     ah, bl[0], bl[1]);
            mma_bf16(c[2 * p],     al, bh[0], bh[1]);
            mma_bf16(c[2 * p + 1], ah, bh[2], bh[3]);
            mma_bf16(c[2 * p + 1], ah, bl[2], bl[3]);
            mma_bf16(c[2 * p + 1], al, bh[2], bh[3]);
        }
    }

    // Epilogue: fragment rows r0g/r1g, cols j*8 + c0 + {0,1}
    const float* aS = (const float*)(sm + OFF_A);
    float s0A = 0.f, s1A = 0.f, s0B = 0.f, s1B = 0.f;
#pragma unroll
    for (int j = 0; j < 8; j++) {
        int col = j * 8 + c0;
        float a0 = aS[col], a1 = aS[col + 1];
        s0A += c[j][0] * a0 + c[j][1] * a1;
        s1A += c[j][2] * a0 + c[j][3] * a1;
        float b0 = aS[64 + col], b1 = aS[64 + col + 1];
        s0B += c[j + 8][0] * b0 + c[j + 8][1] * b1;
        s1B += c[j + 8][2] * b0 + c[j + 8][3] * b1;
        if (ok0) {
            *(float2*)&Ya[(size_t)r0g * DO + col] = make_float2(c[j][0], c[j][1]);
            *(float2*)&Yb[(size_t)r0g * DO + col] = make_float2(c[j + 8][0], c[j + 8][1]);
        }
        if (ok1) {
            *(float2*)&Ya[(size_t)r1g * DO + col] = make_float2(c[j][2], c[j][3]);
            *(float2*)&Yb[(size_t)r1g * DO + col] = make_float2(c[j + 8][2], c[j + 8][3]);
        }
    }
    // Reduce over the 4 lanes sharing a row (lane&3)
#pragma unroll
    for (int o = 1; o <= 2; o <<= 1) {
        s0A += __shfl_xor_sync(0xffffffffu, s0A, o);
        s1A += __shfl_xor_sync(0xffffffffu, s1A, o);
        s0B += __shfl_xor_sync(0xffffffffu, s0B, o);
        s1B += __shfl_xor_sync(0xffffffffu, s1B, o);
    }
    if ((lane & 3) == 0) {
        if (ok0) { sA[r0g] = s0A; sB[r0g] = s0B; }
        if (ok1) { sA[r1g] = s1A; sB[r1g] = s1B; }
    }
}

// ---------------------------------------------------------------------------
// Edge scatter: 16 lanes per edge, 4 edges per group (batched gathers, MLP=4)
// ---------------------------------------------------------------------------
__global__ __launch_bounds__(256) void edge_k(
    const int* __restrict__ src, const int* __restrict__ tgt,
    const float* __restrict__ ss, const float* __restrict__ ts,
    const float4* __restrict__ sx4, float4* __restrict__ msg4,
    float* __restrict__ den, int E)
{
    int g = blockIdx.x * 16 + (threadIdx.x >> 4);
    int lane = threadIdx.x & 15;
    int e0 = g * 4;
    if (e0 >= E) return;
    int n = E - e0; if (n > 4) n = 4;

    int s[4], t[4];
#pragma unroll
    for (int j = 0; j < 4; j++) {
        int e = e0 + (j < n ? j : 0);
        s[j] = __ldg(&src[e]);
        t[j] = __ldg(&tgt[e]);
    }
    float att[4];
#pragma unroll
    for (int j = 0; j < 4; j++) {
        float sc = __ldg(&ss[s[j]]) + __ldg(&ts[t[j]]);
        float sl = sc >= 0.f ? sc : 0.2f * sc;
        att[j] = expf(sl);
    }
    float4 v[4];
#pragma unroll
    for (int j = 0; j < 4; j++) v[j] = __ldg(&sx4[(size_t)s[j] * 16 + lane]);
#pragma unroll
    for (int j = 0; j < 4; j++) {
        if (j < n) {
            float4* p = &msg4[(size_t)t[j] * 16 + lane];
            asm volatile("red.global.add.v4.f32 [%0], {%1,%2,%3,%4};"
                         :: "l"(p), "f"(v[j].x * att[j]), "f"(v[j].y * att[j]),
                            "f"(v[j].z * att[j]), "f"(v[j].w * att[j]) : "memory");
            if (lane == 0) atomicAdd(&den[t[j]], att[j]);
        }
    }
}

// ---------------------------------------------------------------------------
// Finalize: out = tx + msg / (den + eps)
// ---------------------------------------------------------------------------
__global__ __launch_bounds__(256) void final_k(
    const float4* __restrict__ txp, const float4* __restrict__ msg,
    const float* __restrict__ den, float4* __restrict__ out, int n4)
{
    int i = blockIdx.x * blockDim.x + threadIdx.x;
    if (i >= n4) return;
    int node = i >> 4;
    float inv = 1.f / (den[node] + 1e-6f);
    float4 m = msg[i];
    float4 t = txp[i];
    out[i] = make_float4(t.x + m.x * inv, t.y + m.y * inv,
                         t.z + m.z * inv, t.w + m.w * inv);
}

// ---------------------------------------------------------------------------
extern "C" void kernel_launch(void* const* d_in, const int* in_sizes, int n_in,
                              void* d_out, int out_size)
{
    const float* x_user   = (const float*)d_in[0];
    const float* x_item   = (const float*)d_in[1];
    const float* W_ui_src = (const float*)d_in[2];
    const float* W_ui_tgt = (const float*)d_in[3];
    const float* W_iu_src = (const float*)d_in[4];
    const float* W_iu_tgt = (const float*)d_in[5];
    const float* a_ui     = (const float*)d_in[6];
    const float* a_iu     = (const float*)d_in[7];
    const int*   edge_ui  = (const int*)d_in[8];
    const int*   edge_iu  = (const int*)d_in[9];
    float* out = (float*)d_out;

    const int Nu  = in_sizes[0] / DI;
    const int Ni  = in_sizes[1] / DI;
    const int Eui = in_sizes[8] / 2;
    const int Eiu = in_sizes[9] / 2;

    float* base = nullptr;
    cudaGetSymbolAddress((void**)&base, g_scratch);
    __nv_bfloat16 *B1hi, *B1lo, *B2hi, *B2lo;
    cudaGetSymbolAddress((void**)&B1hi, g_B1hi);
    cudaGetSymbolAddress((void**)&B1lo, g_B1lo);
    cudaGetSymbolAddress((void**)&B2hi, g_B2hi);
    cudaGetSymbolAddress((void**)&B2lo, g_B2lo);

    float* s = base;
    float* sx_ui  = s; s += (size_t)Nu * DO;
    float* tx_iu  = s; s += (size_t)Nu * DO;
    float* sx_iu  = s; s += (size_t)Ni * DO;
    float* tx_ui  = s; s += (size_t)Ni * DO;
    float* msg_ui = s; s += (size_t)Ni * DO;
    float* msg_iu = s; s += (size_t)Nu * DO;
    float* den_ui = s; s += Ni;
    float* den_iu = s; s += Nu;
    float* ss_ui  = s; s += Nu;
    float* ts_ui  = s; s += Ni;
    float* ss_iu  = s; s += Ni;
    float* ts_iu  = s; s += Nu;

    cudaFuncSetAttribute(gemm_tc, cudaFuncAttributeMaxDynamicSharedMemorySize, SMEM_TOT);

    // Zero msg + den
    {
        size_t zf = (size_t)(Ni + Nu) * DO + (size_t)Ni + (size_t)Nu;
        int blocks = (int)((zf / 4 + 255) / 256) + 1;
        zero_k<<<blocks, 256>>>(msg_ui, zf);
    }

    // Prep split/transposed B images
    pre_w_k<<<64, 256>>>(W_ui_src, W_iu_tgt, B1hi, B1lo);
    pre_w_k<<<64, 256>>>(W_iu_src, W_ui_tgt, B2hi, B2lo);

    // HMMA projections + fused node scores
    gemm_tc<<<(Nu + 127) / 128, 256, SMEM_TOT>>>(
        x_user, B1hi, B1lo, sx_ui, tx_iu, a_ui, a_iu + DO, ss_ui, ts_iu, Nu);
    gemm_tc<<<(Ni + 127) / 128, 256, SMEM_TOT>>>(
        x_item, B2hi, B2lo, sx_iu, tx_ui, a_iu, a_ui + DO, ss_iu, ts_ui, Ni);

    // Edge scatter (4 edges per 16-lane group)
    edge_k<<<(Eui + 63) / 64, 256>>>(
        edge_ui, edge_ui + Eui, ss_ui, ts_ui,
        (const float4*)sx_ui, (float4*)msg_ui, den_ui, Eui);
    edge_k<<<(Eiu + 63) / 64, 256>>>(
        edge_iu, edge_iu + Eiu, ss_iu, ts_iu,
        (const float4*)sx_iu, (float4*)msg_iu, den_iu, Eiu);

    // Finalize
    {
        int n4u = Nu * 16, n4i = Ni * 16;
        final_k<<<(n4u + 255) / 256, 256>>>(
            (const float4*)tx_iu, (const float4*)msg_iu, den_iu,
            (float4*)out, n4u);
        final_k<<<(n4i + 255) / 256, 256>>>(
            (const float4*)tx_ui, (const float4*)msg_ui, den_ui,
            (float4*)(out + (size_t)Nu * DO), n4i);
    }
}

// round 6
// speedup vs baseline: 1.6056x; 1.0430x over previous
#include <cuda_runtime.h>
#include <cuda_bf16.h>
#include <cstdint>
#include <cstddef>

#define DI 128
#define DO 64
#define NMAX 100000

// B image layout: [128 n][136 k-pitch] bf16 (272B row pitch)
#define BPITCH 136

// ---------------------------------------------------------------------------
// Scratch
// ---------------------------------------------------------------------------
__device__ __align__(16) float g_scratch[6 * (size_t)NMAX * DO + 6 * (size_t)NMAX];
__device__ __align__(16) __nv_bfloat16 g_B1hi[128 * BPITCH], g_B1lo[128 * BPITCH];
__device__ __align__(16) __nv_bfloat16 g_B2hi[128 * BPITCH], g_B2lo[128 * BPITCH];

__device__ __forceinline__ uint32_t smem_u32(const void* p) {
    uint32_t a;
    asm("{ .reg .u64 t; cvta.to.shared.u64 t, %1; cvt.u32.u64 %0, t; }"
        : "=r"(a) : "l"(p));
    return a;
}

__device__ __forceinline__ void ldm_x4(uint32_t* r, uint32_t addr) {
    asm volatile("ldmatrix.sync.aligned.m8n8.x4.shared.b16 {%0,%1,%2,%3}, [%4];"
                 : "=r"(r[0]), "=r"(r[1]), "=r"(r[2]), "=r"(r[3]) : "r"(addr));
}

__device__ __forceinline__ void mma_bf16(float* c, const uint32_t* a,
                                         uint32_t b0, uint32_t b1) {
    asm volatile("mma.sync.aligned.m16n8k16.row.col.f32.bf16.bf16.f32 "
                 "{%0,%1,%2,%3}, {%4,%5,%6,%7}, {%8,%9}, {%0,%1,%2,%3};"
                 : "+f"(c[0]), "+f"(c[1]), "+f"(c[2]), "+f"(c[3])
                 : "r"(a[0]), "r"(a[1]), "r"(a[2]), "r"(a[3]),
                   "r"(b0), "r"(b1));
}

// Pack two floats into bf16x2 (hi) and the residual bf16x2 (lo)
__device__ __forceinline__ void split2(float x, float y, uint32_t& hi, uint32_t& lo) {
    __nv_bfloat162 h = __floats2bfloat162_rn(x, y);
    __nv_bfloat162 l = __floats2bfloat162_rn(x - __bfloat162float(h.x),
                                             y - __bfloat162float(h.y));
    hi = *(uint32_t*)&h;
    lo = *(uint32_t*)&l;
}

// SMEM layout (bytes). B tiles: 128 rows x 272B pitch
#define XPITCH 272
#define OFF_A    0                       // aA[64], aB[64] floats (512B)
#define OFF_BHI  512
#define OFF_BLO  (OFF_BHI + 128 * XPITCH)
#define SMEM_TOT (OFF_BLO + 128 * XPITCH)   // 70144

// ---------------------------------------------------------------------------
// Arg bundles for merged launches
// ---------------------------------------------------------------------------
struct GA {
    const float* X;
    const __nv_bfloat16* Bhi;
    const __nv_bfloat16* Blo;
    float* Ya; float* Yb;
    const float* aA; const float* aB;
    float* sA; float* sB;
    int N;
};
struct EA {
    const int* src; const int* tgt;
    const float* ss; const float* ts;
    const float4* sx4; float4* msg4; float* den;
    int E;
};

// ---------------------------------------------------------------------------
// Prep (merged): B[n][k] = Wa[k][n] (n<64) else Wb[k][n-64], split bf16 hi/lo.
// Blocks 0..63 -> set 1, 64..127 -> set 2.
// ---------------------------------------------------------------------------
__global__ void pre_w_k(const float* __restrict__ Wa1, const float* __restrict__ Wb1,
                        __nv_bfloat16* __restrict__ B1hi, __nv_bfloat16* __restrict__ B1lo,
                        const float* __restrict__ Wa2, const float* __restrict__ Wb2,
                        __nv_bfloat16* __restrict__ B2hi, __nv_bfloat16* __restrict__ B2lo) {
    int which = blockIdx.x >> 6;
    int idx = (blockIdx.x & 63) * 256 + threadIdx.x;
    const float* Wa = which ? Wa2 : Wa1;
    const float* Wb = which ? Wb2 : Wb1;
    __nv_bfloat16* Bhi = which ? B2hi : B1hi;
    __nv_bfloat16* Blo = which ? B2lo : B1lo;
    int n = idx >> 7, k = idx & 127;
    float w = (n < 64) ? Wa[k * 64 + n] : Wb[k * 64 + (n - 64)];
    __nv_bfloat16 hi = __float2bfloat16(w);
    __nv_bfloat16 lo = __float2bfloat16(w - __bfloat162float(hi));
    Bhi[n * BPITCH + k] = hi;
    Blo[n * BPITCH + k] = lo;
}

// ---------------------------------------------------------------------------
// zero kernel
// ---------------------------------------------------------------------------
__global__ void zero_k(float* __restrict__ p, size_t nf) {
    size_t i = ((size_t)blockIdx.x * blockDim.x + threadIdx.x) * 4;
    if (i + 4 <= nf) {
        *(float4*)(p + i) = make_float4(0.f, 0.f, 0.f, 0.f);
    } else {
        for (; i < nf; i++) p[i] = 0.f;
    }
}

// ---------------------------------------------------------------------------
// Merged HMMA GEMM, warp tiling 4M x 2N: each warp owns 32 rows x 64 cols.
// Split-bf16: D = Xhi*Bhi + Xhi*Blo + Xlo*Bhi (fp32 acc).
// X fragments loaded directly from gmem; B via ldmatrix (half strip per warp).
// Fused per-row score epilogue. 2 CTAs/SM.
// ---------------------------------------------------------------------------
__global__ __launch_bounds__(256, 2)
void gemm_tc(GA g1, GA g2, int nb1)
{
    extern __shared__ char sm[];
    const uint32_t sb = smem_u32(sm);
    const int tid = threadIdx.x, wid = tid >> 5, lane = tid & 31;

    const bool first = blockIdx.x < nb1;
    const GA g = first ? g1 : g2;
    const int row0 = (first ? blockIdx.x : blockIdx.x - nb1) * 128;

    // Copy pre-split B images into smem
    {
        const float4* bh = (const float4*)g.Bhi;
        const float4* bl = (const float4*)g.Blo;
        float4* sh = (float4*)(sm + OFF_BHI);
        float4* sl = (float4*)(sm + OFF_BLO);
        const int n4 = 128 * BPITCH * 2 / 16;   // 2176 float4
        for (int i = tid; i < n4; i += 256) {
            sh[i] = bh[i];
            sl[i] = bl[i];
        }
    }
    if (tid < 64)       ((float*)(sm + OFF_A))[tid] = __ldg(&g.aA[tid]);
    else if (tid < 128) ((float*)(sm + OFF_A))[tid] = __ldg(&g.aB[tid - 64]);

    const int wm = wid & 3, wn = wid >> 2;
    const int c0 = (lane & 3) * 2;

    // 4 rows per lane: mtile0 rows {+0,+8}, mtile1 rows {+16,+24}
    const int rb = row0 + wm * 32 + (lane >> 2);
    int rows[4] = {rb, rb + 8, rb + 16, rb + 24};
    bool ok[4];
    const float* xp[4];
#pragma unroll
    for (int m = 0; m < 4; m++) {
        ok[m] = rows[m] < g.N;
        xp[m] = g.X + (size_t)(ok[m] ? rows[m] : 0) * DI + c0;
    }

    __syncthreads();

    // Accumulators: c[mtile*8 + ntile][4], mtile 0..1, ntile 0..7 (8 cols each)
    float c[16][4];
#pragma unroll
    for (int j = 0; j < 16; j++)
#pragma unroll
        for (int q = 0; q < 4; q++) c[j][q] = 0.f;

    // ldmatrix B lane-address components
    const int brow = (lane & 7) + ((lane >> 4) & 1) * 8;
    const int bkk  = ((lane >> 3) & 1) * 8;
    const uint32_t bbase = sb + (wn * 64 + brow) * XPITCH + bkk * 2;

#pragma unroll
    for (int s = 0; s < 8; s++) {
        const int ks = s * 16;
        // A fragments straight from gmem (2 m-tiles)
        float2 v[8];
#pragma unroll
        for (int m = 0; m < 4; m++) {
            v[m]     = ok[m] ? *(const float2*)(xp[m] + ks)     : make_float2(0.f, 0.f);
            v[m + 4] = ok[m] ? *(const float2*)(xp[m] + ks + 8) : make_float2(0.f, 0.f);
        }
        uint32_t ah0[4], al0[4], ah1[4], al1[4];
        split2(v[0].x, v[0].y, ah0[0], al0[0]);
        split2(v[1].x, v[1].y, ah0[1], al0[1]);
        split2(v[4].x, v[4].y, ah0[2], al0[2]);
        split2(v[5].x, v[5].y, ah0[3], al0[3]);
        split2(v[2].x, v[2].y, ah1[0], al1[0]);
        split2(v[3].x, v[3].y, ah1[1], al1[1]);
        split2(v[6].x, v[6].y, ah1[2], al1[2]);
        split2(v[7].x, v[7].y, ah1[3], al1[3]);

#pragma unroll
        for (int p = 0; p < 4; p++) {
            uint32_t bh[4], bl[4];
            uint32_t boff = (uint32_t)(p * 16) * XPITCH + ks * 2;
            ldm_x4(bh, bbase + OFF_BHI + boff);
            ldm_x4(bl, bbase + OFF_BLO + boff);
            // mtile 0
            mma_bf16(c[2 * p],     ah0, bh[0], bh[1]);
            mma_bf16(c[2 * p],     ah0, bl[0], bl[1]);
            mma_bf16(c[2 * p],     al0, bh[0], bh[1]);
            mma_bf16(c[2 * p + 1], ah0, bh[2], bh[3]);
            mma_bf16(c[2 * p + 1], ah0, bl[2], bl[3]);
            mma_bf16(c[2 * p + 1], al0, bh[2], bh[3]);
            // mtile 1
            mma_bf16(c[8 + 2 * p],     ah1, bh[0], bh[1]);
            mma_bf16(c[8 + 2 * p],     ah1, bl[0], bl[1]);
            mma_bf16(c[8 + 2 * p],     al1, bh[0], bh[1]);
            mma_bf16(c[8 + 2 * p + 1], ah1, bh[2], bh[3]);
            mma_bf16(c[8 + 2 * p + 1], ah1, bl[2], bl[3]);
            mma_bf16(c[8 + 2 * p + 1], al1, bh[2], bh[3]);
        }
    }

    // Epilogue: wn==0 -> Ya + score A; wn==1 -> Yb + score B
    const float* av = (const float*)(sm + OFF_A) + wn * 64;
    float* Y    = wn ? g.Yb : g.Ya;
    float* sOut = wn ? g.sB : g.sA;

    float sc[4] = {0.f, 0.f, 0.f, 0.f};
#pragma unroll
    for (int n = 0; n < 8; n++) {
        int col = n * 8 + c0;
        float a0 = av[col], a1 = av[col + 1];
        sc[0] += c[n][0] * a0 + c[n][1] * a1;
        sc[1] += c[n][2] * a0 + c[n][3] * a1;
        sc[2] += c[8 + n][0] * a0 + c[8 + n][1] * a1;
        sc[3] += c[8 + n][2] * a0 + c[8 + n][3] * a1;
        if (ok[0]) *(float2*)&Y[(size_t)rows[0] * DO + col] = make_float2(c[n][0], c[n][1]);
        if (ok[1]) *(float2*)&Y[(size_t)rows[1] * DO + col] = make_float2(c[n][2], c[n][3]);
        if (ok[2]) *(float2*)&Y[(size_t)rows[2] * DO + col] = make_float2(c[8 + n][0], c[8 + n][1]);
        if (ok[3]) *(float2*)&Y[(size_t)rows[3] * DO + col] = make_float2(c[8 + n][2], c[8 + n][3]);
    }
#pragma unroll
    for (int o = 1; o <= 2; o <<= 1) {
#pragma unroll
        for (int m = 0; m < 4; m++) sc[m] += __shfl_xor_sync(0xffffffffu, sc[m], o);
    }
    if ((lane & 3) == 0) {
#pragma unroll
        for (int m = 0; m < 4; m++)
            if (ok[m]) sOut[rows[m]] = sc[m];
    }
}

// ---------------------------------------------------------------------------
// Merged edge scatter: 16 lanes per edge, 4 edges per group.
// ---------------------------------------------------------------------------
__global__ __launch_bounds__(256) void edge_k(EA e1, EA e2, int nb1)
{
    const bool first = blockIdx.x < (unsigned)nb1;
    const EA a = first ? e1 : e2;
    const int bb = first ? blockIdx.x : blockIdx.x - nb1;

    int g = bb * 16 + (threadIdx.x >> 4);
    int lane = threadIdx.x & 15;
    int e0 = g * 4;
    if (e0 >= a.E) return;
    int n = a.E - e0; if (n > 4) n = 4;

    int s[4], t[4];
#pragma unroll
    for (int j = 0; j < 4; j++) {
        int e = e0 + (j < n ? j : 0);
        s[j] = __ldg(&a.src[e]);
        t[j] = __ldg(&a.tgt[e]);
    }
    float att[4];
#pragma unroll
    for (int j = 0; j < 4; j++) {
        float scr = __ldg(&a.ss[s[j]]) + __ldg(&a.ts[t[j]]);
        float sl = scr >= 0.f ? scr : 0.2f * scr;
        att[j] = expf(sl);
    }
    float4 v[4];
#pragma unroll
    for (int j = 0; j < 4; j++) v[j] = __ldg(&a.sx4[(size_t)s[j] * 16 + lane]);
#pragma unroll
    for (int j = 0; j < 4; j++) {
        if (j < n) {
            float4* p = &a.msg4[(size_t)t[j] * 16 + lane];
            asm volatile("red.global.add.v4.f32 [%0], {%1,%2,%3,%4};"
                         :: "l"(p), "f"(v[j].x * att[j]), "f"(v[j].y * att[j]),
                            "f"(v[j].z * att[j]), "f"(v[j].w * att[j]) : "memory");
            if (lane == 0) atomicAdd(&a.den[t[j]], att[j]);
        }
    }
}

// ---------------------------------------------------------------------------
// Merged finalize: out = tx + msg / (den + eps), user region then item region
// ---------------------------------------------------------------------------
__global__ __launch_bounds__(256) void final_k(
    const float4* __restrict__ txu, const float4* __restrict__ msgu,
    const float* __restrict__ denu,
    const float4* __restrict__ txi, const float4* __restrict__ msgi,
    const float* __restrict__ deni,
    float4* __restrict__ out, int n4u, int n4tot)
{
    int i = blockIdx.x * blockDim.x + threadIdx.x;
    if (i >= n4tot) return;
    const float4* txp; const float4* msg; const float* den;
    int li;
    if (i < n4u) { txp = txu; msg = msgu; den = denu; li = i; }
    else         { txp = txi; msg = msgi; den = deni; li = i - n4u; }
    int node = li >> 4;
    float inv = 1.f / (den[node] + 1e-6f);
    float4 m = msg[li];
    float4 t = txp[li];
    out[i] = make_float4(t.x + m.x * inv, t.y + m.y * inv,
                         t.z + m.z * inv, t.w + m.w * inv);
}

// ---------------------------------------------------------------------------
extern "C" void kernel_launch(void* const* d_in, const int* in_sizes, int n_in,
                              void* d_out, int out_size)
{
    const float* x_user   = (const float*)d_in[0];
    const float* x_item   = (const float*)d_in[1];
    const float* W_ui_src = (const float*)d_in[2];
    const float* W_ui_tgt = (const float*)d_in[3];
    const float* W_iu_src = (const float*)d_in[4];
    const float* W_iu_tgt = (const float*)d_in[5];
    const float* a_ui     = (const float*)d_in[6];
    const float* a_iu     = (const float*)d_in[7];
    const int*   edge_ui  = (const int*)d_in[8];
    const int*   edge_iu  = (const int*)d_in[9];
    float* out = (float*)d_out;

    const int Nu  = in_sizes[0] / DI;
    const int Ni  = in_sizes[1] / DI;
    const int Eui = in_sizes[8] / 2;
    const int Eiu = in_sizes[9] / 2;

    float* base = nullptr;
    cudaGetSymbolAddress((void**)&base, g_scratch);
    __nv_bfloat16 *B1hi, *B1lo, *B2hi, *B2lo;
    cudaGetSymbolAddress((void**)&B1hi, g_B1hi);
    cudaGetSymbolAddress((void**)&B1lo, g_B1lo);
    cudaGetSymbolAddress((void**)&B2hi, g_B2hi);
    cudaGetSymbolAddress((void**)&B2lo, g_B2lo);

    float* s = base;
    float* sx_ui  = s; s += (size_t)Nu * DO;
    float* tx_iu  = s; s += (size_t)Nu * DO;
    float* sx_iu  = s; s += (size_t)Ni * DO;
    float* tx_ui  = s; s += (size_t)Ni * DO;
    float* msg_ui = s; s += (size_t)Ni * DO;
    float* msg_iu = s; s += (size_t)Nu * DO;
    float* den_ui = s; s += Ni;
    float* den_iu = s; s += Nu;
    float* ss_ui  = s; s += Nu;
    float* ts_ui  = s; s += Ni;
    float* ss_iu  = s; s += Ni;
    float* ts_iu  = s; s += Nu;

    cudaFuncSetAttribute(gemm_tc, cudaFuncAttributeMaxDynamicSharedMemorySize, SMEM_TOT);

    // Zero msg + den (contiguous region starting at msg_ui)
    {
        size_t zf = (size_t)(Ni + Nu) * DO + (size_t)Ni + (size_t)Nu;
        int blocks = (int)((zf / 4 + 255) / 256) + 1;
        zero_k<<<blocks, 256>>>(msg_ui, zf);
    }

    // Prep split/transposed B images (merged)
    pre_w_k<<<128, 256>>>(W_ui_src, W_iu_tgt, B1hi, B1lo,
                          W_iu_src, W_ui_tgt, B2hi, B2lo);

    // Merged HMMA projections + fused node scores
    {
        GA g1 = {x_user, B1hi, B1lo, sx_ui, tx_iu, a_ui, a_iu + DO, ss_ui, ts_iu, Nu};
        GA g2 = {x_item, B2hi, B2lo, sx_iu, tx_ui, a_iu, a_ui + DO, ss_iu, ts_ui, Ni};
        int nb1 = (Nu + 127) / 128;
        int nb2 = (Ni + 127) / 128;
        gemm_tc<<<nb1 + nb2, 256, SMEM_TOT>>>(g1, g2, nb1);
    }

    // Merged edge scatter
    {
        EA e1 = {edge_ui, edge_ui + Eui, ss_ui, ts_ui,
                 (const float4*)sx_ui, (float4*)msg_ui, den_ui, Eui};
        EA e2 = {edge_iu, edge_iu + Eiu, ss_iu, ts_iu,
                 (const float4*)sx_iu, (float4*)msg_iu, den_iu, Eiu};
        int nb1 = (Eui + 63) / 64;
        int nb2 = (Eiu + 63) / 64;
        edge_k<<<nb1 + nb2, 256>>>(e1, e2, nb1);
    }

    // Merged finalize
    {
        int n4u = Nu * 16, n4tot = (Nu + Ni) * 16;
        final_k<<<(n4tot + 255) / 256, 256>>>(
            (const float4*)tx_iu, (const float4*)msg_iu, den_iu,
            (const float4*)tx_ui, (const float4*)msg_ui, den_ui,
            (float4*)out, n4u, n4tot);
    }
}